// round 3
// baseline (speedup 1.0000x reference)
#include <cuda_runtime.h>

// HybridQuanvolutionFraudNet: the reference's final op is
//     logits = h @ wf.T + bf            # shape [B, 1]
//     return jax.nn.log_softmax(logits, axis=-1)
// log_softmax over a size-1 axis is identically 0.0 (shifted = x - max(x) = 0,
// logsumexp(0) = 0). Every upstream op (4-qubit statevector quanvolution,
// two tanh layers, final linear) is dead computation. Output is exactly
// zeros([out_size], float32). Verified Round 1: passed, rel_err = 0.0 bitwise.
//
// Round 1: single tiny kernel = 4.58 µs wall / 3.36 µs ncu kernel time,
// all pipes ~0% — pure per-node launch overhead. This round (resubmit of
// Round 2, which died to container-acquisition infra failure) replaces the
// kernel launch with a graph MEMSET node: no SM grid launch, no CTA
// scheduling, lighter dispatch. No allocation, fully graph-capturable.

// Fallback kernel kept for reference (unused this round):
__global__ void zero_out_kernel(float* __restrict__ out, int n) {
    int i = (blockIdx.x * blockDim.x + threadIdx.x) * 4;
    if (i < n) *reinterpret_cast<float4*>(out + i) = make_float4(0.f, 0.f, 0.f, 0.f);
}

extern "C" void kernel_launch(void* const* d_in, const int* in_sizes, int n_in,
                              void* d_out, int out_size) {
    (void)d_in; (void)in_sizes; (void)n_in;
    // 0x00-byte fill == 0.0f for IEEE-754 float32. Captured as a graph memset node.
    cudaMemsetAsync(d_out, 0, (size_t)out_size * sizeof(float), 0);
}